// round 13
// baseline (speedup 1.0000x reference)
#include <cuda_runtime.h>
#include <cuda_fp16.h>
#include <cstdint>

// Problem constants
#define BATCH 8
#define FIN   64
#define NPTS  4096
#define FOUT  64
#define KNN   20
#define KA    26                     // init list size (tiles 0-7)
#define REFK  28                     // k2b approx-select size
#define CAP   512                    // candidate buffer capacity per row

#define FULLMASK 0xffffffffu
#define BIGF 3.0e38f

// ---------------------------------------------------------------------------
// Device scratch (no allocations allowed)
// ---------------------------------------------------------------------------
__device__ float g_Yt[BATCH * NPTS * FOUT];                    // W2 . x_n
__device__ float g_Ct[BATCH * NPTS * FOUT];                    // (W1-W2).x_n + b
__device__ __align__(16) float g_sq[BATCH * NPTS];             // ||x_n||^2
__device__ int      g_idx[BATCH * NPTS * KNN];                 // refined knn indices
__device__ unsigned g_buf[(size_t)BATCH * NPTS * CAP];         // candidate buffer
__device__ int      g_cnt[BATCH * NPTS];                       // buffer counts
__device__ float    g_w[BATCH * NPTS];                         // per-row threshold
__device__ __align__(16) __half g_p[BATCH * NPTS * 128];       // [hi(64)|lo(64)]

// ---------------------------------------------------------------------------
// Portable PTX helpers (compile fine for compute_103)
// ---------------------------------------------------------------------------
__device__ __forceinline__ uint32_t smem_u32(const void* p) {
    uint32_t a;
    asm("{ .reg .u64 t; cvta.to.shared.u64 t, %1; cvt.u32.u64 %0, t; }" : "=r"(a) : "l"(p));
    return a;
}
__device__ __forceinline__ void ldsm_x4(uint32_t addr, uint32_t* r) {
    asm volatile("ldmatrix.sync.aligned.m8n8.x4.shared.b16 {%0,%1,%2,%3}, [%4];"
        : "=r"(r[0]), "=r"(r[1]), "=r"(r[2]), "=r"(r[3]) : "r"(addr));
}
__device__ __forceinline__ void mma16816(float* c, const uint32_t* a, const uint32_t* b) {
    asm volatile("mma.sync.aligned.m16n8k16.row.col.f32.f16.f16.f32 "
        "{%0,%1,%2,%3}, {%4,%5,%6,%7}, {%8,%9}, {%0,%1,%2,%3};"
        : "+f"(c[0]), "+f"(c[1]), "+f"(c[2]), "+f"(c[3])
        : "r"(a[0]), "r"(a[1]), "r"(a[2]), "r"(a[3]), "r"(b[0]), "r"(b[1]));
}
__device__ __forceinline__ unsigned long long pack2(float lo, float hi) {
    unsigned long long r;
    asm("mov.b64 %0, {%1, %2};" : "=l"(r) : "f"(lo), "f"(hi));
    return r;
}
__device__ __forceinline__ void unpack2(unsigned long long v, float& lo, float& hi) {
    asm("mov.b64 {%0, %1}, %2;" : "=f"(lo), "=f"(hi) : "l"(v));
}
__device__ __forceinline__ void fma2(unsigned long long& c, unsigned long long a,
                                     unsigned long long b) {
    asm("fma.rn.f32x2 %0, %1, %2, %0;" : "+l"(c) : "l"(a), "l"(b));
}
__device__ __forceinline__ float2 h2pair(unsigned h, unsigned l) {
    float2 a = __half22float2(*reinterpret_cast<const __half2*>(&h));
    float2 b = __half22float2(*reinterpret_cast<const __half2*>(&l));
    return make_float2(a.x + b.x, a.y + b.y);
}
// ordered-int key packed with 12-bit candidate index in the low bits
__device__ __forceinline__ unsigned packkey(float k, int m) {
    unsigned u = __float_as_uint(k);
    u ^= (unsigned)((int)u >> 31) | 0x80000000u;
    return (u & 0xFFFFF000u) | (unsigned)m;
}
#define CP_ASYNC16(dst, src) \
    asm volatile("cp.async.cg.shared.global [%0], [%1], 16;" :: "r"(dst), "l"(src))
#define CP_COMMIT() asm volatile("cp.async.commit_group;" ::: "memory")
#define CP_WAIT0()  asm volatile("cp.async.wait_group 0;" ::: "memory")

// ---------------------------------------------------------------------------
// Kernel 1: per-point features Yt/Ct (f32x2 packed fma), sq norms, fp16 hi/lo
// ---------------------------------------------------------------------------
__global__ __launch_bounds__(128) void k1_features(
    const float* __restrict__ x, const float* __restrict__ W,
    const float* __restrict__ bvec)
{
    __shared__ float W2s[64][32];
    __shared__ float Wds[64][32];
    __shared__ float bs[32];

    const int bb   = blockIdx.y;
    const int n0   = blockIdx.x * 128;
    const int half = blockIdx.z;
    const int tid  = threadIdx.x;

    for (int idx = tid; idx < 64 * 32; idx += 128) {
        int f = idx >> 5, o = idx & 31;
        int og = half * 32 + o;
        float w1 = W[og * 128 + f];
        float w2 = W[og * 128 + 64 + f];
        W2s[f][o] = w2;
        Wds[f][o] = w1 - w2;
    }
    if (tid < 32) bs[tid] = bvec[half * 32 + tid];
    __syncthreads();

    const float* xb = x + (size_t)bb * FIN * NPTS;
    const int n = n0 + tid;

    float xr[64];
#pragma unroll
    for (int f = 0; f < 64; ++f) xr[f] = xb[f * NPTS + n];

    uint4* pdst = (uint4*)(g_p + ((size_t)(bb * NPTS + n)) * 128);
    if (half == 0) {
        float sq = 0.f;
#pragma unroll
        for (int f = 0; f < 64; ++f) sq = fmaf(xr[f], xr[f], sq);
        g_sq[bb * NPTS + n] = sq;
#pragma unroll
        for (int q = 0; q < 8; ++q) {
            __half2 h[4];
#pragma unroll
            for (int e = 0; e < 4; ++e)
                h[e] = __floats2half2_rn(xr[q * 8 + 2 * e], xr[q * 8 + 2 * e + 1]);
            pdst[q] = make_uint4(*(unsigned*)&h[0], *(unsigned*)&h[1],
                                 *(unsigned*)&h[2], *(unsigned*)&h[3]);
        }
    } else {
#pragma unroll
        for (int q = 0; q < 8; ++q) {
            float r[8];
#pragma unroll
            for (int e = 0; e < 8; ++e) {
                float xf = xr[q * 8 + e];
                r[e] = xf - __half2float(__float2half_rn(xf));
            }
            __half2 h[4];
#pragma unroll
            for (int e = 0; e < 4; ++e)
                h[e] = __floats2half2_rn(r[2 * e], r[2 * e + 1]);
            pdst[8 + q] = make_uint4(*(unsigned*)&h[0], *(unsigned*)&h[1],
                                     *(unsigned*)&h[2], *(unsigned*)&h[3]);
        }
    }

    const size_t base = ((size_t)(bb * NPTS + n)) * 64 + half * 32;

    unsigned long long ya2[16], ca2[16];
#pragma unroll
    for (int p = 0; p < 16; ++p) {
        ya2[p] = pack2(0.f, 0.f);
        ca2[p] = pack2(bs[2 * p], bs[2 * p + 1]);
    }

#pragma unroll 4
    for (int f = 0; f < 64; ++f) {
        const unsigned long long a2 = pack2(xr[f], xr[f]);
#pragma unroll
        for (int oo = 0; oo < 32; oo += 4) {
            float4 w2 = *(const float4*)&W2s[f][oo];
            float4 wd = *(const float4*)&Wds[f][oo];
            fma2(ya2[oo / 2],     a2, pack2(w2.x, w2.y));
            fma2(ya2[oo / 2 + 1], a2, pack2(w2.z, w2.w));
            fma2(ca2[oo / 2],     a2, pack2(wd.x, wd.y));
            fma2(ca2[oo / 2 + 1], a2, pack2(wd.z, wd.w));
        }
    }
    float4* Yp = (float4*)(g_Yt + base);
    float4* Cp = (float4*)(g_Ct + base);
#pragma unroll
    for (int q = 0; q < 8; ++q) {
        float y0, y1, y2, y3, c0, c1, c2, c3;
        unpack2(ya2[2 * q], y0, y1);
        unpack2(ya2[2 * q + 1], y2, y3);
        unpack2(ca2[2 * q], c0, c1);
        unpack2(ca2[2 * q + 1], c2, c3);
        Yp[q] = make_float4(y0, y1, y2, y3);
        Cp[q] = make_float4(c0, c1, c2, c3);
    }
}

// ---------------------------------------------------------------------------
// Shared GEMM config for k2a / k2: 64 query rows per CTA, 8 warps (2 row
// groups x 4 col groups), warp tile 32x16, tiles of 64 candidate cols.
// ---------------------------------------------------------------------------
#define SMA_BYTES 8192               // A: 64 rows x 128B (hi)
#define SMB_OFF   8192               // B: 2 bufs x 8KB
#define DSS 66

// ---------------------------------------------------------------------------
// Kernel 2a: init — tiles 0..7 (512 candidates), warp-coop top-26 per row,
// seeds g_buf/g_cnt and publishes threshold g_w.
// grid 512 (8 batches x 64 row-blocks of 64), 256 threads.
// ---------------------------------------------------------------------------
#define K2A_DS   24576
#define K2A_SMEM (K2A_DS + 64 * DSS * 4)    // 41472

__global__ __launch_bounds__(256, 2) void k2a_init(void)
{
    extern __shared__ char sm[];
    const uint32_t smem_base = smem_u32(sm);
    float* Ds = (float*)(sm + K2A_DS);

    const int tid  = threadIdx.x;
    const int wid  = tid >> 5;
    const int lane = tid & 31;
    const int wr   = wid & 1;
    const int wc   = wid >> 1;

    const int bb = blockIdx.x >> 6;
    const int n0 = (blockIdx.x & 63) * 64;

    const __half* gp  = g_p + (size_t)bb * NPTS * 128;
    const float*  sqg = g_sq + (size_t)bb * NPTS;

    // A panel (hi), swizzled
    for (int idx = tid; idx < 512; idx += 256) {
        int r = idx >> 3, ch = idx & 7;
        uint4 v = *(const uint4*)(gp + (size_t)(n0 + r) * 128 + ch * 8);
        *(uint4*)(sm + r * 128 + ((ch ^ (r & 7)) << 4)) = v;
    }

    auto loadB = [&](int t, int buf) {
        const __half* src0 = gp + (size_t)t * 64 * 128;
        uint32_t dst0 = smem_base + SMB_OFF + buf * 8192;
#pragma unroll
        for (int k = 0; k < 2; ++k) {
            int idx = tid + k * 256;
            int r = idx >> 3, ch = idx & 7;
            CP_ASYNC16(dst0 + r * 128 + ((ch ^ (r & 7)) << 4),
                       src0 + (size_t)r * 128 + ch * 8);
        }
        CP_COMMIT();
    };

    unsigned lv[8];
#pragma unroll
    for (int r = 0; r < 8; ++r) lv[r] = 0xFFFFFFFFu;
    const int srow0 = wid * 8;

    loadB(0, 0);

#pragma unroll 1
    for (int t = 0; t < 8; ++t) {
        CP_WAIT0();
        __syncthreads();                 // B visible; Ds free (prev scan done)
        if (t + 1 < 8) loadB(t + 1, (t + 1) & 1);

        float acc[2][2][4];
#pragma unroll
        for (int mt = 0; mt < 2; ++mt)
#pragma unroll
            for (int nt = 0; nt < 2; ++nt)
#pragma unroll
                for (int e = 0; e < 4; ++e) acc[mt][nt][e] = 0.f;

        const uint32_t bbase = smem_base + SMB_OFF + (t & 1) * 8192;
#pragma unroll
        for (int ks = 0; ks < 4; ++ks) {
            uint32_t ah[2][4], bh[4];
            const int acha = ks * 2 + (lane >> 4);
            const int bcha = ks * 2 + ((lane >> 3) & 1);
#pragma unroll
            for (int mt = 0; mt < 2; ++mt) {
                int row = wr * 32 + mt * 16 + (lane & 15);
                ldsm_x4(smem_base + row * 128 + ((acha ^ (row & 7)) << 4), ah[mt]);
            }
            {
                int row = wc * 16 + (lane & 7) + ((lane >> 4) << 3);
                ldsm_x4(bbase + row * 128 + ((bcha ^ (row & 7)) << 4), bh);
            }
#pragma unroll
            for (int mt = 0; mt < 2; ++mt)
#pragma unroll
                for (int nt = 0; nt < 2; ++nt)
                    mma16816(acc[mt][nt], ah[mt], &bh[nt * 2]);
        }

        // stage Ds
#pragma unroll
        for (int mt = 0; mt < 2; ++mt) {
            int row0 = wr * 32 + mt * 16 + (lane >> 2);
#pragma unroll
            for (int nt = 0; nt < 2; ++nt) {
                int col0 = wc * 16 + nt * 8 + 2 * (lane & 3);
                Ds[row0 * DSS + col0]           = acc[mt][nt][0];
                Ds[row0 * DSS + col0 + 1]       = acc[mt][nt][1];
                Ds[(row0 + 8) * DSS + col0]     = acc[mt][nt][2];
                Ds[(row0 + 8) * DSS + col0 + 1] = acc[mt][nt][3];
            }
        }
        __syncthreads();

        // scan: warp-coop top-26 over tile t's 64 candidates
        const float2 sqv = *(const float2*)(sqg + t * 64 + 2 * lane);
        const int m0g = t * 64 + 2 * lane;
#pragma unroll
        for (int r = 0; r < 8; ++r) {
            const int nrowr = n0 + srow0 + r;
            const float2 d2 = *(const float2*)&Ds[(srow0 + r) * DSS + 2 * lane];
            const float k0 = fmaf(-2.0f, d2.x, sqv.x);
            const float k1 = fmaf(-2.0f, d2.y, sqv.y);
            const unsigned p0 = (m0g == nrowr)     ? 0xFFFFFFFFu : packkey(k0, m0g);
            const unsigned p1 = (m0g + 1 == nrowr) ? 0xFFFFFFFFu : packkey(k1, m0g + 1);

            const unsigned w = __shfl_sync(FULLMASK, lv[r], KA - 1);
            unsigned b = __ballot_sync(FULLMASK, min(p0, p1) < w);
            while (b) {
                const int s = __ffs(b) - 1;
                b &= b - 1;
                const unsigned P0 = __shfl_sync(FULLMASK, p0, s);
                const unsigned P1 = __shfl_sync(FULLMASK, p1, s);
#pragma unroll
                for (int e = 0; e < 2; ++e) {
                    const unsigned P = e ? P1 : P0;
                    if (P < w) {
                        const unsigned up = __shfl_up_sync(FULLMASK, lv[r], 1);
                        const bool pv    = lv[r] > P;
                        const bool pprev = (lane == 0) ? false : (up > P);
                        lv[r] = pv ? (pprev ? up : P) : lv[r];
                    }
                }
            }
        }
    }

    // seed buffer + publish threshold
#pragma unroll
    for (int r = 0; r < 8; ++r) {
        const int growg = bb * NPTS + n0 + srow0 + r;
        if (lane < KA) g_buf[(size_t)growg * CAP + lane] = lv[r];
        if (lane == KA - 1) {
            unsigned u = lv[r] & 0xFFFFF000u;            // trunc-down in key space
            u = (u & 0x80000000u) ? (u ^ 0x80000000u) : ~u;
            g_w[growg] = __uint_as_float(u);
        }
        if (lane == 0) g_cnt[growg] = KA;
    }
}

// ---------------------------------------------------------------------------
// Kernel 2: tiles 8..63 — GEMM + in-register threshold scan + global append.
// grid 512, 256 threads. No Ds, no ballots, no per-tile scan sync.
// ---------------------------------------------------------------------------
#define K2_SQ    24576
#define K2_SMEM  (K2_SQ + 512)       // 25088

__global__ __launch_bounds__(256, 2) void k2_scan(void)
{
    extern __shared__ char sm[];
    const uint32_t smem_base = smem_u32(sm);

    const int tid  = threadIdx.x;
    const int wid  = tid >> 5;
    const int lane = tid & 31;
    const int wr   = wid & 1;
    const int wc   = wid >> 1;

    const int bb = blockIdx.x >> 6;
    const int n0 = (blockIdx.x & 63) * 64;

    const __half* gp = g_p + (size_t)bb * NPTS * 128;

    // A panel (hi), swizzled
    for (int idx = tid; idx < 512; idx += 256) {
        int r = idx >> 3, ch = idx & 7;
        uint4 v = *(const uint4*)(gp + (size_t)(n0 + r) * 128 + ch * 8);
        *(uint4*)(sm + r * 128 + ((ch ^ (r & 7)) << 4)) = v;
    }

    auto loadB = [&](int t, int buf) {
        const __half* src0 = gp + (size_t)t * 64 * 128;
        uint32_t dst0 = smem_base + SMB_OFF + buf * 8192;
#pragma unroll
        for (int k = 0; k < 2; ++k) {
            int idx = tid + k * 256;
            int r = idx >> 3, ch = idx & 7;
            CP_ASYNC16(dst0 + r * 128 + ((ch ^ (r & 7)) << 4),
                       src0 + (size_t)r * 128 + ch * 8);
        }
        if (tid < 16)
            CP_ASYNC16(smem_base + K2_SQ + buf * 256 + tid * 16,
                       g_sq + bb * NPTS + t * 64 + tid * 4);
        CP_COMMIT();
    };

    // this thread's 4 accumulator rows + thresholds
    const int rbase = n0 + wr * 32 + (lane >> 2);
    int   growg[4];
    float wf[4];
#pragma unroll
    for (int q = 0; q < 4; ++q) {
        const int rr = rbase + (q >> 1) * 16 + (q & 1) * 8;   // q = mt*2+h
        growg[q] = bb * NPTS + rr;
        wf[q]    = g_w[bb * NPTS + rr];
    }

    loadB(8, 0);

#pragma unroll 1
    for (int t = 8; t < 64; ++t) {
        CP_WAIT0();
        __syncthreads();
        if (t + 1 < 64) loadB(t + 1, (t + 1) & 1);

        float acc[2][2][4];
#pragma unroll
        for (int mt = 0; mt < 2; ++mt)
#pragma unroll
            for (int nt = 0; nt < 2; ++nt)
#pragma unroll
                for (int e = 0; e < 4; ++e) acc[mt][nt][e] = 0.f;

        const uint32_t bbase = smem_base + SMB_OFF + (t & 1) * 8192;
#pragma unroll
        for (int ks = 0; ks < 4; ++ks) {
            uint32_t ah[2][4], bh[4];
            const int acha = ks * 2 + (lane >> 4);
            const int bcha = ks * 2 + ((lane >> 3) & 1);
#pragma unroll
            for (int mt = 0; mt < 2; ++mt) {
                int row = wr * 32 + mt * 16 + (lane & 15);
                ldsm_x4(smem_base + row * 128 + ((acha ^ (row & 7)) << 4), ah[mt]);
            }
            {
                int row = wc * 16 + (lane & 7) + ((lane >> 4) << 3);
                ldsm_x4(bbase + row * 128 + ((bcha ^ (row & 7)) << 4), bh);
            }
#pragma unroll
            for (int mt = 0; mt < 2; ++mt)
#pragma unroll
                for (int nt = 0; nt < 2; ++nt)
                    mma16816(acc[mt][nt], ah[mt], &bh[nt * 2]);
        }

        // threshold scan straight from accumulators (no staging, no collectives)
        const float* sqt = (const float*)(sm + K2_SQ + (t & 1) * 256);
#pragma unroll
        for (int mt = 0; mt < 2; ++mt)
#pragma unroll
            for (int nt = 0; nt < 2; ++nt) {
                const int cl = wc * 16 + nt * 8 + 2 * (lane & 3);
                const float2 sq2 = *(const float2*)&sqt[cl];
                const int c0 = t * 64 + cl;
#pragma unroll
                for (int h = 0; h < 2; ++h) {
                    const int q = mt * 2 + h;
                    const float k0 = fmaf(-2.0f, acc[mt][nt][h * 2 + 0], sq2.x);
                    const float k1 = fmaf(-2.0f, acc[mt][nt][h * 2 + 1], sq2.y);
                    if (fminf(k0, k1) < wf[q]) {
                        if (k0 < wf[q]) {
                            int pos = atomicAdd(&g_cnt[growg[q]], 1);
                            if (pos < CAP)
                                g_buf[(size_t)growg[q] * CAP + pos] = packkey(k0, c0);
                        }
                        if (k1 < wf[q]) {
                            int pos = atomicAdd(&g_cnt[growg[q]], 1);
                            if (pos < CAP)
                                g_buf[(size_t)growg[q] * CAP + pos] = packkey(k1, c0 + 1);
                        }
                    }
                }
            }
    }
}

// ---------------------------------------------------------------------------
// Kernel 2b: per-row approx-top-28 from buffer, then exact fp32 top-20
// grid 4096, 256 threads (8 warps = 8 rows per CTA)
// ---------------------------------------------------------------------------
__global__ __launch_bounds__(256) void k2b_refine(void)
{
    const int lane = threadIdx.x & 31;
    const int gw   = blockIdx.x * 8 + (threadIdx.x >> 5);
    const int bb   = gw >> 12;
    const int row  = gw & 4095;

    const __half* gp  = g_p + (size_t)bb * NPTS * 128;
    const float*  sqg = g_sq + (size_t)bb * NPTS;

    int cnt = g_cnt[gw];
    if (cnt > CAP) cnt = CAP;
    const unsigned* bufr = g_buf + (size_t)gw * CAP;

    // approx top-REFK (packed, distributed lanes 0..27)
    unsigned lv = 0xFFFFFFFFu;
#pragma unroll 1
    for (int base = 0; base < cnt; base += 32) {
        const unsigned p = (base + lane < cnt) ? bufr[base + lane] : 0xFFFFFFFFu;
        const unsigned w = __shfl_sync(FULLMASK, lv, REFK - 1);
        unsigned b = __ballot_sync(FULLMASK, p < w);
        while (b) {
            const int s = __ffs(b) - 1;
            b &= b - 1;
            const unsigned P = __shfl_sync(FULLMASK, p, s);
            if (P < w) {
                const unsigned up = __shfl_up_sync(FULLMASK, lv, 1);
                const bool pv    = lv > P;
                const bool pprev = (lane == 0) ? false : (up > P);
                lv = pv ? (pprev ? up : P) : lv;
            }
        }
    }

    // exact refine of the 28 survivors (skip self / empty slots)
    const unsigned* pn = (const unsigned*)(gp + (size_t)row * 128);
    const float2 an = h2pair(pn[lane], pn[32 + lane]);

    float mykey = BIGF;
    int   myidx = 0;
#pragma unroll 1
    for (int c = 0; c < REFK; c += 2) {
        const unsigned LA = __shfl_sync(FULLMASK, lv, c);
        const unsigned LB = __shfl_sync(FULLMASK, lv, c + 1);
        const int mA = (int)(LA & 0xFFFu);
        const int mB = (int)(LB & 0xFFFu);
        const unsigned* pA = (const unsigned*)(gp + (size_t)mA * 128);
        const unsigned* pB = (const unsigned*)(gp + (size_t)mB * 128);
        const float2 aA = h2pair(pA[lane], pA[32 + lane]);
        const float2 aB = h2pair(pB[lane], pB[32 + lane]);
        float pa = fmaf(an.x, aA.x, an.y * aA.y);
        float pb = fmaf(an.x, aB.x, an.y * aB.y);
#pragma unroll
        for (int s = 16; s >= 1; s >>= 1) {
            pa += __shfl_xor_sync(FULLMASK, pa, s);
            pb += __shfl_xor_sync(FULLMASK, pb, s);
        }
        float keyA = fmaf(-2.0f, pa, sqg[mA]);
        float keyB = fmaf(-2.0f, pb, sqg[mB]);
        if (LA == 0xFFFFFFFFu || mA == row) keyA = BIGF;
        if (LB == 0xFFFFFFFFu || mB == row) keyB = BIGF;
        if (lane == c)     { mykey = keyA; myidx = mA; }
        if (lane == c + 1) { mykey = keyB; myidx = mB; }
    }

    // exact top-20 select from the 28 exact keys
    float nv = BIGF; int ni = 0;
    float w = BIGF;
#pragma unroll 1
    for (int s = 0; s < REFK; ++s) {
        const float K = __shfl_sync(FULLMASK, mykey, s);
        const int   M = __shfl_sync(FULLMASK, myidx, s);
        if (K < w) {
            const float vprev = __shfl_up_sync(FULLMASK, nv, 1);
            const int   iprev = __shfl_up_sync(FULLMASK, ni, 1);
            const bool pv    = nv > K;
            const bool pprev = (lane == 0) ? false : (vprev > K);
            nv = pv ? (pprev ? vprev : K) : nv;
            ni = pv ? (pprev ? iprev : M) : ni;
            w = __shfl_sync(FULLMASK, nv, KNN - 1);
        }
    }
    if (lane < KNN)
        g_idx[(size_t)gw * KNN + lane] = ni;
}

// ---------------------------------------------------------------------------
// Kernel 3: gather-max epilogue + transpose to [b][o][n]
// ---------------------------------------------------------------------------
__global__ __launch_bounds__(256) void k3_epilogue(float* __restrict__ out)
{
    __shared__ float outs[64][65];
    const int bb  = blockIdx.y;
    const int n0  = blockIdx.x * 64;
    const int tid = threadIdx.x;
    const int w    = tid >> 5;
    const int lane = tid & 31;

    const float* Y = g_Yt + (size_t)bb * NPTS * 64;
    const float* C = g_Ct + (size_t)bb * NPTS * 64;

#pragma unroll 1
    for (int s = 0; s < 8; ++s) {
        int nn = w * 8 + s;
        int n  = n0 + nn;
        int jj = 0;
        if (lane < KNN) jj = g_idx[((size_t)(bb * NPTS + n)) * KNN + lane];
        float m0v = -3.0e38f, m1v = -3.0e38f;
#pragma unroll
        for (int i = 0; i < KNN; ++i) {
            int j = __shfl_sync(0xffffffffu, jj, i);
            const float* yr = Y + (size_t)j * 64;
            m0v = fmaxf(m0v, yr[lane]);
            m1v = fmaxf(m1v, yr[lane + 32]);
        }
        outs[nn][lane]      = m0v + C[(size_t)n * 64 + lane];
        outs[nn][lane + 32] = m1v + C[(size_t)n * 64 + lane + 32];
    }
    __syncthreads();

    float* ob = out + (size_t)bb * FOUT * NPTS;
#pragma unroll
    for (int it = 0; it < 16; ++it) {
        int lin = it * 256 + tid;
        int o  = lin >> 6;
        int nn = lin & 63;
        ob[o * NPTS + n0 + nn] = outs[nn][o];
    }
}

// ---------------------------------------------------------------------------
extern "C" void kernel_launch(void* const* d_in, const int* in_sizes, int n_in,
                              void* d_out, int out_size)
{
    const float* x    = (const float*)d_in[0];
    const float* W    = (const float*)d_in[1];
    const float* bvec = (const float*)d_in[2];
    float* out        = (float*)d_out;

    cudaFuncSetAttribute(k2a_init, cudaFuncAttributeMaxDynamicSharedMemorySize, K2A_SMEM);
    cudaFuncSetAttribute(k2_scan,  cudaFuncAttributeMaxDynamicSharedMemorySize, K2_SMEM);

    k1_features<<<dim3(NPTS / 128, BATCH, 2), 128>>>(x, W, bvec);
    k2a_init<<<BATCH * (NPTS / 64), 256, K2A_SMEM>>>();
    k2_scan<<<BATCH * (NPTS / 64), 256, K2_SMEM>>>();
    k2b_refine<<<BATCH * NPTS / 8, 256>>>();
    k3_epilogue<<<dim3(NPTS / 64, BATCH), 256>>>(out);
}

// round 14
// speedup vs baseline: 1.9646x; 1.9646x over previous
#include <cuda_runtime.h>
#include <cuda_fp16.h>
#include <cstdint>

// Problem constants
#define BATCH 8
#define FIN   64
#define NPTS  4096
#define FOUT  64
#define KNN   20
#define KA    26                     // init list size (sample tiles)
#define REFK  28                     // k2b approx-select size
#define CAP   512                    // candidate buffer capacity per row
#define SMP   16                     // sample tiles (16*64 = 1024 candidates)

#define FULLMASK 0xffffffffu
#define BIGF 3.0e38f

// ---------------------------------------------------------------------------
// Device scratch (no allocations allowed)
// ---------------------------------------------------------------------------
__device__ float g_Yt[BATCH * NPTS * FOUT];                    // W2 . x_n
__device__ float g_Ct[BATCH * NPTS * FOUT];                    // (W1-W2).x_n + b
__device__ __align__(16) float g_sq[BATCH * NPTS];             // ||x_n||^2
__device__ int      g_idx[BATCH * NPTS * KNN];                 // refined knn indices
__device__ unsigned g_buf[(size_t)BATCH * NPTS * CAP];         // candidate buffer
__device__ int      g_cnt[BATCH * NPTS];                       // buffer counts
__device__ float    g_w[BATCH * NPTS];                         // per-row threshold
__device__ __align__(16) __half g_p[BATCH * NPTS * 128];       // [hi(64)|lo(64)]

// ---------------------------------------------------------------------------
// Portable PTX helpers (compile fine for compute_103)
// ---------------------------------------------------------------------------
__device__ __forceinline__ uint32_t smem_u32(const void* p) {
    uint32_t a;
    asm("{ .reg .u64 t; cvta.to.shared.u64 t, %1; cvt.u32.u64 %0, t; }" : "=r"(a) : "l"(p));
    return a;
}
__device__ __forceinline__ void ldsm_x4(uint32_t addr, uint32_t* r) {
    asm volatile("ldmatrix.sync.aligned.m8n8.x4.shared.b16 {%0,%1,%2,%3}, [%4];"
        : "=r"(r[0]), "=r"(r[1]), "=r"(r[2]), "=r"(r[3]) : "r"(addr));
}
__device__ __forceinline__ void mma16816(float* c, const uint32_t* a, const uint32_t* b) {
    asm volatile("mma.sync.aligned.m16n8k16.row.col.f32.f16.f16.f32 "
        "{%0,%1,%2,%3}, {%4,%5,%6,%7}, {%8,%9}, {%0,%1,%2,%3};"
        : "+f"(c[0]), "+f"(c[1]), "+f"(c[2]), "+f"(c[3])
        : "r"(a[0]), "r"(a[1]), "r"(a[2]), "r"(a[3]), "r"(b[0]), "r"(b[1]));
}
__device__ __forceinline__ unsigned long long pack2(float lo, float hi) {
    unsigned long long r;
    asm("mov.b64 %0, {%1, %2};" : "=l"(r) : "f"(lo), "f"(hi));
    return r;
}
__device__ __forceinline__ void unpack2(unsigned long long v, float& lo, float& hi) {
    asm("mov.b64 {%0, %1}, %2;" : "=f"(lo), "=f"(hi) : "l"(v));
}
__device__ __forceinline__ void fma2(unsigned long long& c, unsigned long long a,
                                     unsigned long long b) {
    asm("fma.rn.f32x2 %0, %1, %2, %0;" : "+l"(c) : "l"(a), "l"(b));
}
__device__ __forceinline__ float2 h2pair(unsigned h, unsigned l) {
    float2 a = __half22float2(*reinterpret_cast<const __half2*>(&h));
    float2 b = __half22float2(*reinterpret_cast<const __half2*>(&l));
    return make_float2(a.x + b.x, a.y + b.y);
}
// ordered-int key packed with 12-bit candidate index in the low bits
__device__ __forceinline__ unsigned packkey(float k, int m) {
    unsigned u = __float_as_uint(k);
    u ^= (unsigned)((int)u >> 31) | 0x80000000u;
    return (u & 0xFFFFF000u) | (unsigned)m;
}
#define CP_ASYNC16(dst, src) \
    asm volatile("cp.async.cg.shared.global [%0], [%1], 16;" :: "r"(dst), "l"(src))
#define CP_COMMIT() asm volatile("cp.async.commit_group;" ::: "memory")
#define CP_WAIT0()  asm volatile("cp.async.wait_group 0;" ::: "memory")

// ---------------------------------------------------------------------------
// Kernel 1: per-point features Yt/Ct (f32x2 packed fma), sq norms, fp16 hi/lo
// ---------------------------------------------------------------------------
__global__ __launch_bounds__(128) void k1_features(
    const float* __restrict__ x, const float* __restrict__ W,
    const float* __restrict__ bvec)
{
    __shared__ float W2s[64][32];
    __shared__ float Wds[64][32];
    __shared__ float bs[32];

    const int bb   = blockIdx.y;
    const int n0   = blockIdx.x * 128;
    const int half = blockIdx.z;
    const int tid  = threadIdx.x;

    for (int idx = tid; idx < 64 * 32; idx += 128) {
        int f = idx >> 5, o = idx & 31;
        int og = half * 32 + o;
        float w1 = W[og * 128 + f];
        float w2 = W[og * 128 + 64 + f];
        W2s[f][o] = w2;
        Wds[f][o] = w1 - w2;
    }
    if (tid < 32) bs[tid] = bvec[half * 32 + tid];
    __syncthreads();

    const float* xb = x + (size_t)bb * FIN * NPTS;
    const int n = n0 + tid;

    float xr[64];
#pragma unroll
    for (int f = 0; f < 64; ++f) xr[f] = xb[f * NPTS + n];

    uint4* pdst = (uint4*)(g_p + ((size_t)(bb * NPTS + n)) * 128);
    if (half == 0) {
        float sq = 0.f;
#pragma unroll
        for (int f = 0; f < 64; ++f) sq = fmaf(xr[f], xr[f], sq);
        g_sq[bb * NPTS + n] = sq;
#pragma unroll
        for (int q = 0; q < 8; ++q) {
            __half2 h[4];
#pragma unroll
            for (int e = 0; e < 4; ++e)
                h[e] = __floats2half2_rn(xr[q * 8 + 2 * e], xr[q * 8 + 2 * e + 1]);
            pdst[q] = make_uint4(*(unsigned*)&h[0], *(unsigned*)&h[1],
                                 *(unsigned*)&h[2], *(unsigned*)&h[3]);
        }
    } else {
#pragma unroll
        for (int q = 0; q < 8; ++q) {
            float r[8];
#pragma unroll
            for (int e = 0; e < 8; ++e) {
                float xf = xr[q * 8 + e];
                r[e] = xf - __half2float(__float2half_rn(xf));
            }
            __half2 h[4];
#pragma unroll
            for (int e = 0; e < 4; ++e)
                h[e] = __floats2half2_rn(r[2 * e], r[2 * e + 1]);
            pdst[8 + q] = make_uint4(*(unsigned*)&h[0], *(unsigned*)&h[1],
                                     *(unsigned*)&h[2], *(unsigned*)&h[3]);
        }
    }

    const size_t base = ((size_t)(bb * NPTS + n)) * 64 + half * 32;

    unsigned long long ya2[16], ca2[16];
#pragma unroll
    for (int p = 0; p < 16; ++p) {
        ya2[p] = pack2(0.f, 0.f);
        ca2[p] = pack2(bs[2 * p], bs[2 * p + 1]);
    }

#pragma unroll 4
    for (int f = 0; f < 64; ++f) {
        const unsigned long long a2 = pack2(xr[f], xr[f]);
#pragma unroll
        for (int oo = 0; oo < 32; oo += 4) {
            float4 w2 = *(const float4*)&W2s[f][oo];
            float4 wd = *(const float4*)&Wds[f][oo];
            fma2(ya2[oo / 2],     a2, pack2(w2.x, w2.y));
            fma2(ya2[oo / 2 + 1], a2, pack2(w2.z, w2.w));
            fma2(ca2[oo / 2],     a2, pack2(wd.x, wd.y));
            fma2(ca2[oo / 2 + 1], a2, pack2(wd.z, wd.w));
        }
    }
    float4* Yp = (float4*)(g_Yt + base);
    float4* Cp = (float4*)(g_Ct + base);
#pragma unroll
    for (int q = 0; q < 8; ++q) {
        float y0, y1, y2, y3, c0, c1, c2, c3;
        unpack2(ya2[2 * q], y0, y1);
        unpack2(ya2[2 * q + 1], y2, y3);
        unpack2(ca2[2 * q], c0, c1);
        unpack2(ca2[2 * q + 1], c2, c3);
        Yp[q] = make_float4(y0, y1, y2, y3);
        Cp[q] = make_float4(c0, c1, c2, c3);
    }
}

// ---------------------------------------------------------------------------
// Shared GEMM config for k2a / k2: 64 query rows per CTA, 8 warps (2 row
// groups x 4 col groups), warp tile 32x16, tiles of 64 candidate cols.
// ---------------------------------------------------------------------------
#define SMB_OFF 8192                 // B: 2 bufs x 8KB (A occupies [0,8192))
#define DSS 66

// ---------------------------------------------------------------------------
// Kernel 2a: init — tiles 0..15 (1024 candidates), warp-coop top-26 per row,
// seeds g_buf and publishes threshold g_w.
// grid 512 (8 batches x 64 row-blocks of 64), 256 threads.
// ---------------------------------------------------------------------------
#define K2A_DS   24576
#define K2A_SMEM (K2A_DS + 64 * DSS * 4)    // 41472

__global__ __launch_bounds__(256, 2) void k2a_init(void)
{
    extern __shared__ char sm[];
    const uint32_t smem_base = smem_u32(sm);
    float* Ds = (float*)(sm + K2A_DS);

    const int tid  = threadIdx.x;
    const int wid  = tid >> 5;
    const int lane = tid & 31;
    const int wr   = wid & 1;
    const int wc   = wid >> 1;

    const int bb = blockIdx.x >> 6;
    const int n0 = (blockIdx.x & 63) * 64;

    const __half* gp  = g_p + (size_t)bb * NPTS * 128;
    const float*  sqg = g_sq + (size_t)bb * NPTS;

    // A panel (hi), swizzled
    for (int idx = tid; idx < 512; idx += 256) {
        int r = idx >> 3, ch = idx & 7;
        uint4 v = *(const uint4*)(gp + (size_t)(n0 + r) * 128 + ch * 8);
        *(uint4*)(sm + r * 128 + ((ch ^ (r & 7)) << 4)) = v;
    }

    auto loadB = [&](int t, int buf) {
        const __half* src0 = gp + (size_t)t * 64 * 128;
        uint32_t dst0 = smem_base + SMB_OFF + buf * 8192;
#pragma unroll
        for (int k = 0; k < 2; ++k) {
            int idx = tid + k * 256;
            int r = idx >> 3, ch = idx & 7;
            CP_ASYNC16(dst0 + r * 128 + ((ch ^ (r & 7)) << 4),
                       src0 + (size_t)r * 128 + ch * 8);
        }
        CP_COMMIT();
    };

    unsigned lv[8];
#pragma unroll
    for (int r = 0; r < 8; ++r) lv[r] = 0xFFFFFFFFu;
    const int srow0 = wid * 8;

    loadB(0, 0);

#pragma unroll 1
    for (int t = 0; t < SMP; ++t) {
        CP_WAIT0();
        __syncthreads();                 // B visible; Ds free (prev scan done)
        if (t + 1 < SMP) loadB(t + 1, (t + 1) & 1);

        float acc[2][2][4];
#pragma unroll
        for (int mt = 0; mt < 2; ++mt)
#pragma unroll
            for (int nt = 0; nt < 2; ++nt)
#pragma unroll
                for (int e = 0; e < 4; ++e) acc[mt][nt][e] = 0.f;

        const uint32_t bbase = smem_base + SMB_OFF + (t & 1) * 8192;
#pragma unroll
        for (int ks = 0; ks < 4; ++ks) {
            uint32_t ah[2][4], bh[4];
            const int acha = ks * 2 + (lane >> 4);
            const int bcha = ks * 2 + ((lane >> 3) & 1);
#pragma unroll
            for (int mt = 0; mt < 2; ++mt) {
                int row = wr * 32 + mt * 16 + (lane & 15);
                ldsm_x4(smem_base + row * 128 + ((acha ^ (row & 7)) << 4), ah[mt]);
            }
            {
                int row = wc * 16 + (lane & 7) + ((lane >> 4) << 3);
                ldsm_x4(bbase + row * 128 + ((bcha ^ (row & 7)) << 4), bh);
            }
#pragma unroll
            for (int mt = 0; mt < 2; ++mt)
#pragma unroll
                for (int nt = 0; nt < 2; ++nt)
                    mma16816(acc[mt][nt], ah[mt], &bh[nt * 2]);
        }

        // stage Ds
#pragma unroll
        for (int mt = 0; mt < 2; ++mt) {
            int row0 = wr * 32 + mt * 16 + (lane >> 2);
#pragma unroll
            for (int nt = 0; nt < 2; ++nt) {
                int col0 = wc * 16 + nt * 8 + 2 * (lane & 3);
                Ds[row0 * DSS + col0]           = acc[mt][nt][0];
                Ds[row0 * DSS + col0 + 1]       = acc[mt][nt][1];
                Ds[(row0 + 8) * DSS + col0]     = acc[mt][nt][2];
                Ds[(row0 + 8) * DSS + col0 + 1] = acc[mt][nt][3];
            }
        }
        __syncthreads();

        // scan: warp-coop top-26 over tile t's 64 candidates
        const float2 sqv = *(const float2*)(sqg + t * 64 + 2 * lane);
        const int m0g = t * 64 + 2 * lane;
#pragma unroll
        for (int r = 0; r < 8; ++r) {
            const int nrowr = n0 + srow0 + r;
            const float2 d2 = *(const float2*)&Ds[(srow0 + r) * DSS + 2 * lane];
            const float k0 = fmaf(-2.0f, d2.x, sqv.x);
            const float k1 = fmaf(-2.0f, d2.y, sqv.y);
            const unsigned p0 = (m0g == nrowr)     ? 0xFFFFFFFFu : packkey(k0, m0g);
            const unsigned p1 = (m0g + 1 == nrowr) ? 0xFFFFFFFFu : packkey(k1, m0g + 1);

            const unsigned w = __shfl_sync(FULLMASK, lv[r], KA - 1);
            unsigned b = __ballot_sync(FULLMASK, min(p0, p1) < w);
            while (b) {
                const int s = __ffs(b) - 1;
                b &= b - 1;
                const unsigned P0 = __shfl_sync(FULLMASK, p0, s);
                const unsigned P1 = __shfl_sync(FULLMASK, p1, s);
#pragma unroll
                for (int e = 0; e < 2; ++e) {
                    const unsigned P = e ? P1 : P0;
                    if (P < w) {
                        const unsigned up = __shfl_up_sync(FULLMASK, lv[r], 1);
                        const bool pv    = lv[r] > P;
                        const bool pprev = (lane == 0) ? false : (up > P);
                        lv[r] = pv ? (pprev ? up : P) : lv[r];
                    }
                }
            }
        }
    }

    // seed buffer + publish threshold
#pragma unroll
    for (int r = 0; r < 8; ++r) {
        const int growg = bb * NPTS + n0 + srow0 + r;
        if (lane < KA) g_buf[(size_t)growg * CAP + lane] = lv[r];
        if (lane == KA - 1) {
            unsigned u = lv[r] & 0xFFFFF000u;            // trunc-down in key space
            u = (u & 0x80000000u) ? (u ^ 0x80000000u) : ~u;
            g_w[growg] = __uint_as_float(u);
        }
    }
}

// ---------------------------------------------------------------------------
// Kernel 2: tiles 16..63 — GEMM + in-register threshold scan + append via
// SMEM row counters (no global atomics). grid 512, 256 threads.
// ---------------------------------------------------------------------------
#define K2_SQ    24576
#define K2_CNT   25088               // 64 ints = 256B
#define K2_SMEM  (K2_CNT + 256)      // 25344

__global__ __launch_bounds__(256, 2) void k2_scan(void)
{
    extern __shared__ char sm[];
    const uint32_t smem_base = smem_u32(sm);
    int* cnts = (int*)(sm + K2_CNT);

    const int tid  = threadIdx.x;
    const int wid  = tid >> 5;
    const int lane = tid & 31;
    const int wr   = wid & 1;
    const int wc   = wid >> 1;

    const int bb = blockIdx.x >> 6;
    const int n0 = (blockIdx.x & 63) * 64;

    const __half* gp = g_p + (size_t)bb * NPTS * 128;

    // A panel (hi), swizzled
    for (int idx = tid; idx < 512; idx += 256) {
        int r = idx >> 3, ch = idx & 7;
        uint4 v = *(const uint4*)(gp + (size_t)(n0 + r) * 128 + ch * 8);
        *(uint4*)(sm + r * 128 + ((ch ^ (r & 7)) << 4)) = v;
    }
    if (tid < 64) cnts[tid] = KA;        // k2a seeded exactly KA entries

    auto loadB = [&](int t, int buf) {
        const __half* src0 = gp + (size_t)t * 64 * 128;
        uint32_t dst0 = smem_base + SMB_OFF + buf * 8192;
#pragma unroll
        for (int k = 0; k < 2; ++k) {
            int idx = tid + k * 256;
            int r = idx >> 3, ch = idx & 7;
            CP_ASYNC16(dst0 + r * 128 + ((ch ^ (r & 7)) << 4),
                       src0 + (size_t)r * 128 + ch * 8);
        }
        if (tid < 16)
            CP_ASYNC16(smem_base + K2_SQ + buf * 256 + tid * 16,
                       g_sq + bb * NPTS + t * 64 + tid * 4);
        CP_COMMIT();
    };

    // this thread's 4 accumulator rows: local counter idx + buffer base + w
    const int rloc0 = wr * 32 + (lane >> 2);
    int    rloc[4];
    size_t bufb[4];
    float  wf[4];
#pragma unroll
    for (int q = 0; q < 4; ++q) {
        const int rl = rloc0 + (q >> 1) * 16 + (q & 1) * 8;   // q = mt*2+h
        rloc[q] = rl;
        bufb[q] = (size_t)(bb * NPTS + n0 + rl) * CAP;
        wf[q]   = g_w[bb * NPTS + n0 + rl];
    }

    loadB(SMP, 0);

#pragma unroll 1
    for (int t = SMP; t < 64; ++t) {
        CP_WAIT0();
        __syncthreads();
        if (t + 1 < 64) loadB(t + 1, (t + 1) & 1);

        float acc[2][2][4];
#pragma unroll
        for (int mt = 0; mt < 2; ++mt)
#pragma unroll
            for (int nt = 0; nt < 2; ++nt)
#pragma unroll
                for (int e = 0; e < 4; ++e) acc[mt][nt][e] = 0.f;

        const uint32_t bbase = smem_base + SMB_OFF + (t & 1) * 8192;
#pragma unroll
        for (int ks = 0; ks < 4; ++ks) {
            uint32_t ah[2][4], bh[4];
            const int acha = ks * 2 + (lane >> 4);
            const int bcha = ks * 2 + ((lane >> 3) & 1);
#pragma unroll
            for (int mt = 0; mt < 2; ++mt) {
                int row = wr * 32 + mt * 16 + (lane & 15);
                ldsm_x4(smem_base + row * 128 + ((acha ^ (row & 7)) << 4), ah[mt]);
            }
            {
                int row = wc * 16 + (lane & 7) + ((lane >> 4) << 3);
                ldsm_x4(bbase + row * 128 + ((bcha ^ (row & 7)) << 4), bh);
            }
#pragma unroll
            for (int mt = 0; mt < 2; ++mt)
#pragma unroll
                for (int nt = 0; nt < 2; ++nt)
                    mma16816(acc[mt][nt], ah[mt], &bh[nt * 2]);
        }

        // threshold scan straight from accumulators; append via SMEM counter
        const float* sqt = (const float*)(sm + K2_SQ + (t & 1) * 256);
#pragma unroll
        for (int mt = 0; mt < 2; ++mt)
#pragma unroll
            for (int nt = 0; nt < 2; ++nt) {
                const int cl = wc * 16 + nt * 8 + 2 * (lane & 3);
                const float2 sq2 = *(const float2*)&sqt[cl];
                const int c0 = t * 64 + cl;
#pragma unroll
                for (int h = 0; h < 2; ++h) {
                    const int q = mt * 2 + h;
                    const float k0 = fmaf(-2.0f, acc[mt][nt][h * 2 + 0], sq2.x);
                    const float k1 = fmaf(-2.0f, acc[mt][nt][h * 2 + 1], sq2.y);
                    if (fminf(k0, k1) < wf[q]) {
                        if (k0 < wf[q]) {
                            int pos = atomicAdd(&cnts[rloc[q]], 1);
                            if (pos < CAP) g_buf[bufb[q] + pos] = packkey(k0, c0);
                        }
                        if (k1 < wf[q]) {
                            int pos = atomicAdd(&cnts[rloc[q]], 1);
                            if (pos < CAP) g_buf[bufb[q] + pos] = packkey(k1, c0 + 1);
                        }
                    }
                }
            }
    }

    // publish counts
    __syncthreads();
    if (tid < 64) g_cnt[bb * NPTS + n0 + tid] = cnts[tid];
}

// ---------------------------------------------------------------------------
// Kernel 2b: per-row approx-top-28 from buffer, then exact fp32 top-20
// grid 4096, 256 threads (8 warps = 8 rows per CTA)
// ---------------------------------------------------------------------------
__global__ __launch_bounds__(256) void k2b_refine(void)
{
    const int lane = threadIdx.x & 31;
    const int gw   = blockIdx.x * 8 + (threadIdx.x >> 5);
    const int bb   = gw >> 12;
    const int row  = gw & 4095;

    const __half* gp  = g_p + (size_t)bb * NPTS * 128;
    const float*  sqg = g_sq + (size_t)bb * NPTS;

    int cnt = g_cnt[gw];
    if (cnt > CAP) cnt = CAP;
    const unsigned* bufr = g_buf + (size_t)gw * CAP;

    // approx top-REFK (packed, distributed lanes 0..27)
    unsigned lv = 0xFFFFFFFFu;
#pragma unroll 1
    for (int base = 0; base < cnt; base += 32) {
        const unsigned p = (base + lane < cnt) ? bufr[base + lane] : 0xFFFFFFFFu;
        const unsigned w = __shfl_sync(FULLMASK, lv, REFK - 1);
        unsigned b = __ballot_sync(FULLMASK, p < w);
        while (b) {
            const int s = __ffs(b) - 1;
            b &= b - 1;
            const unsigned P = __shfl_sync(FULLMASK, p, s);
            if (P < w) {
                const unsigned up = __shfl_up_sync(FULLMASK, lv, 1);
                const bool pv    = lv > P;
                const bool pprev = (lane == 0) ? false : (up > P);
                lv = pv ? (pprev ? up : P) : lv;
            }
        }
    }

    // exact refine of the 28 survivors (skip self / empty slots)
    const unsigned* pn = (const unsigned*)(gp + (size_t)row * 128);
    const float2 an = h2pair(pn[lane], pn[32 + lane]);

    float mykey = BIGF;
    int   myidx = 0;
#pragma unroll 1
    for (int c = 0; c < REFK; c += 2) {
        const unsigned LA = __shfl_sync(FULLMASK, lv, c);
        const unsigned LB = __shfl_sync(FULLMASK, lv, c + 1);
        const int mA = (int)(LA & 0xFFFu);
        const int mB = (int)(LB & 0xFFFu);
        const unsigned* pA = (const unsigned*)(gp + (size_t)mA * 128);
        const unsigned* pB = (const unsigned*)(gp + (size_t)mB * 128);
        const float2 aA = h2pair(pA[lane], pA[32 + lane]);
        const float2 aB = h2pair(pB[lane], pB[32 + lane]);
        float pa = fmaf(an.x, aA.x, an.y * aA.y);
        float pb = fmaf(an.x, aB.x, an.y * aB.y);
#pragma unroll
        for (int s = 16; s >= 1; s >>= 1) {
            pa += __shfl_xor_sync(FULLMASK, pa, s);
            pb += __shfl_xor_sync(FULLMASK, pb, s);
        }
        float keyA = fmaf(-2.0f, pa, sqg[mA]);
        float keyB = fmaf(-2.0f, pb, sqg[mB]);
        if (LA == 0xFFFFFFFFu || mA == row) keyA = BIGF;
        if (LB == 0xFFFFFFFFu || mB == row) keyB = BIGF;
        if (lane == c)     { mykey = keyA; myidx = mA; }
        if (lane == c + 1) { mykey = keyB; myidx = mB; }
    }

    // exact top-20 select from the 28 exact keys
    float nv = BIGF; int ni = 0;
    float w = BIGF;
#pragma unroll 1
    for (int s = 0; s < REFK; ++s) {
        const float K = __shfl_sync(FULLMASK, mykey, s);
        const int   M = __shfl_sync(FULLMASK, myidx, s);
        if (K < w) {
            const float vprev = __shfl_up_sync(FULLMASK, nv, 1);
            const int   iprev = __shfl_up_sync(FULLMASK, ni, 1);
            const bool pv    = nv > K;
            const bool pprev = (lane == 0) ? false : (vprev > K);
            nv = pv ? (pprev ? vprev : K) : nv;
            ni = pv ? (pprev ? iprev : M) : ni;
            w = __shfl_sync(FULLMASK, nv, KNN - 1);
        }
    }
    if (lane < KNN)
        g_idx[(size_t)gw * KNN + lane] = ni;
}

// ---------------------------------------------------------------------------
// Kernel 3: gather-max epilogue + transpose to [b][o][n]
// ---------------------------------------------------------------------------
__global__ __launch_bounds__(256) void k3_epilogue(float* __restrict__ out)
{
    __shared__ float outs[64][65];
    const int bb  = blockIdx.y;
    const int n0  = blockIdx.x * 64;
    const int tid = threadIdx.x;
    const int w    = tid >> 5;
    const int lane = tid & 31;

    const float* Y = g_Yt + (size_t)bb * NPTS * 64;
    const float* C = g_Ct + (size_t)bb * NPTS * 64;

#pragma unroll 1
    for (int s = 0; s < 8; ++s) {
        int nn = w * 8 + s;
        int n  = n0 + nn;
        int jj = 0;
        if (lane < KNN) jj = g_idx[((size_t)(bb * NPTS + n)) * KNN + lane];
        float m0v = -3.0e38f, m1v = -3.0e38f;
#pragma unroll
        for (int i = 0; i < KNN; ++i) {
            int j = __shfl_sync(0xffffffffu, jj, i);
            const float* yr = Y + (size_t)j * 64;
            m0v = fmaxf(m0v, yr[lane]);
            m1v = fmaxf(m1v, yr[lane + 32]);
        }
        outs[nn][lane]      = m0v + C[(size_t)n * 64 + lane];
        outs[nn][lane + 32] = m1v + C[(size_t)n * 64 + lane + 32];
    }
    __syncthreads();

    float* ob = out + (size_t)bb * FOUT * NPTS;
#pragma unroll
    for (int it = 0; it < 16; ++it) {
        int lin = it * 256 + tid;
        int o  = lin >> 6;
        int nn = lin & 63;
        ob[o * NPTS + n0 + nn] = outs[nn][o];
    }
}

// ---------------------------------------------------------------------------
extern "C" void kernel_launch(void* const* d_in, const int* in_sizes, int n_in,
                              void* d_out, int out_size)
{
    const float* x    = (const float*)d_in[0];
    const float* W    = (const float*)d_in[1];
    const float* bvec = (const float*)d_in[2];
    float* out        = (float*)d_out;

    cudaFuncSetAttribute(k2a_init, cudaFuncAttributeMaxDynamicSharedMemorySize, K2A_SMEM);
    cudaFuncSetAttribute(k2_scan,  cudaFuncAttributeMaxDynamicSharedMemorySize, K2_SMEM);

    k1_features<<<dim3(NPTS / 128, BATCH, 2), 128>>>(x, W, bvec);
    k2a_init<<<BATCH * (NPTS / 64), 256, K2A_SMEM>>>();
    k2_scan<<<BATCH * (NPTS / 64), 256, K2_SMEM>>>();
    k2b_refine<<<BATCH * NPTS / 8, 256>>>();
    k3_epilogue<<<dim3(NPTS / 64, BATCH), 256>>>(out);
}

// round 15
// speedup vs baseline: 2.0790x; 1.0583x over previous
#include <cuda_runtime.h>
#include <cuda_fp16.h>
#include <cstdint>

// Problem constants
#define BATCH 8
#define FIN   64
#define NPTS  4096
#define FOUT  64
#define KNN   20
#define KA    26                     // sample-phase list size
#define REFK  28                     // k2b approx-select size
#define CAP   512                    // candidate buffer capacity per row
#define SMP   16                     // sample tiles (16*64 = 1024 candidates)

#define FULLMASK 0xffffffffu
#define BIGF 3.0e38f

// ---------------------------------------------------------------------------
// Device scratch (no allocations allowed)
// ---------------------------------------------------------------------------
__device__ float g_Yt[BATCH * NPTS * FOUT];                    // W2 . x_n
__device__ float g_Ct[BATCH * NPTS * FOUT];                    // (W1-W2).x_n + b
__device__ __align__(16) float g_sq[BATCH * NPTS];             // ||x_n||^2
__device__ int      g_idx[BATCH * NPTS * KNN];                 // refined knn indices
__device__ unsigned g_buf[(size_t)BATCH * NPTS * CAP];         // candidate buffer
__device__ int      g_cnt[BATCH * NPTS];                       // buffer counts
__device__ __align__(16) __half g_p[BATCH * NPTS * 128];       // [hi(64)|lo(64)]

// ---------------------------------------------------------------------------
// Portable PTX helpers (compile fine for compute_103)
// ---------------------------------------------------------------------------
__device__ __forceinline__ uint32_t smem_u32(const void* p) {
    uint32_t a;
    asm("{ .reg .u64 t; cvta.to.shared.u64 t, %1; cvt.u32.u64 %0, t; }" : "=r"(a) : "l"(p));
    return a;
}
__device__ __forceinline__ void ldsm_x4(uint32_t addr, uint32_t* r) {
    asm volatile("ldmatrix.sync.aligned.m8n8.x4.shared.b16 {%0,%1,%2,%3}, [%4];"
        : "=r"(r[0]), "=r"(r[1]), "=r"(r[2]), "=r"(r[3]) : "r"(addr));
}
__device__ __forceinline__ void mma16816(float* c, const uint32_t* a, const uint32_t* b) {
    asm volatile("mma.sync.aligned.m16n8k16.row.col.f32.f16.f16.f32 "
        "{%0,%1,%2,%3}, {%4,%5,%6,%7}, {%8,%9}, {%0,%1,%2,%3};"
        : "+f"(c[0]), "+f"(c[1]), "+f"(c[2]), "+f"(c[3])
        : "r"(a[0]), "r"(a[1]), "r"(a[2]), "r"(a[3]), "r"(b[0]), "r"(b[1]));
}
__device__ __forceinline__ unsigned long long pack2(float lo, float hi) {
    unsigned long long r;
    asm("mov.b64 %0, {%1, %2};" : "=l"(r) : "f"(lo), "f"(hi));
    return r;
}
__device__ __forceinline__ void unpack2(unsigned long long v, float& lo, float& hi) {
    asm("mov.b64 {%0, %1}, %2;" : "=f"(lo), "=f"(hi) : "l"(v));
}
__device__ __forceinline__ void fma2(unsigned long long& c, unsigned long long a,
                                     unsigned long long b) {
    asm("fma.rn.f32x2 %0, %1, %2, %0;" : "+l"(c) : "l"(a), "l"(b));
}
__device__ __forceinline__ float2 h2pair(unsigned h, unsigned l) {
    float2 a = __half22float2(*reinterpret_cast<const __half2*>(&h));
    float2 b = __half22float2(*reinterpret_cast<const __half2*>(&l));
    return make_float2(a.x + b.x, a.y + b.y);
}
// ordered-int key packed with 12-bit candidate index in the low bits
__device__ __forceinline__ unsigned packkey(float k, int m) {
    unsigned u = __float_as_uint(k);
    u ^= (unsigned)((int)u >> 31) | 0x80000000u;
    return (u & 0xFFFFF000u) | (unsigned)m;
}
#define CP_ASYNC16(dst, src) \
    asm volatile("cp.async.cg.shared.global [%0], [%1], 16;" :: "r"(dst), "l"(src))
#define CP_COMMIT() asm volatile("cp.async.commit_group;" ::: "memory")
#define CP_WAIT0()  asm volatile("cp.async.wait_group 0;" ::: "memory")

// ---------------------------------------------------------------------------
// Kernel 1: per-point features Yt/Ct (f32x2 packed fma), sq norms, fp16 hi/lo
// ---------------------------------------------------------------------------
__global__ __launch_bounds__(128) void k1_features(
    const float* __restrict__ x, const float* __restrict__ W,
    const float* __restrict__ bvec)
{
    __shared__ float W2s[64][32];
    __shared__ float Wds[64][32];
    __shared__ float bs[32];

    const int bb   = blockIdx.y;
    const int n0   = blockIdx.x * 128;
    const int half = blockIdx.z;
    const int tid  = threadIdx.x;

    for (int idx = tid; idx < 64 * 32; idx += 128) {
        int f = idx >> 5, o = idx & 31;
        int og = half * 32 + o;
        float w1 = W[og * 128 + f];
        float w2 = W[og * 128 + 64 + f];
        W2s[f][o] = w2;
        Wds[f][o] = w1 - w2;
    }
    if (tid < 32) bs[tid] = bvec[half * 32 + tid];
    __syncthreads();

    const float* xb = x + (size_t)bb * FIN * NPTS;
    const int n = n0 + tid;

    float xr[64];
#pragma unroll
    for (int f = 0; f < 64; ++f) xr[f] = xb[f * NPTS + n];

    uint4* pdst = (uint4*)(g_p + ((size_t)(bb * NPTS + n)) * 128);
    if (half == 0) {
        float sq = 0.f;
#pragma unroll
        for (int f = 0; f < 64; ++f) sq = fmaf(xr[f], xr[f], sq);
        g_sq[bb * NPTS + n] = sq;
#pragma unroll
        for (int q = 0; q < 8; ++q) {
            __half2 h[4];
#pragma unroll
            for (int e = 0; e < 4; ++e)
                h[e] = __floats2half2_rn(xr[q * 8 + 2 * e], xr[q * 8 + 2 * e + 1]);
            pdst[q] = make_uint4(*(unsigned*)&h[0], *(unsigned*)&h[1],
                                 *(unsigned*)&h[2], *(unsigned*)&h[3]);
        }
    } else {
#pragma unroll
        for (int q = 0; q < 8; ++q) {
            float r[8];
#pragma unroll
            for (int e = 0; e < 8; ++e) {
                float xf = xr[q * 8 + e];
                r[e] = xf - __half2float(__float2half_rn(xf));
            }
            __half2 h[4];
#pragma unroll
            for (int e = 0; e < 4; ++e)
                h[e] = __floats2half2_rn(r[2 * e], r[2 * e + 1]);
            pdst[8 + q] = make_uint4(*(unsigned*)&h[0], *(unsigned*)&h[1],
                                     *(unsigned*)&h[2], *(unsigned*)&h[3]);
        }
    }

    const size_t base = ((size_t)(bb * NPTS + n)) * 64 + half * 32;

    unsigned long long ya2[16], ca2[16];
#pragma unroll
    for (int p = 0; p < 16; ++p) {
        ya2[p] = pack2(0.f, 0.f);
        ca2[p] = pack2(bs[2 * p], bs[2 * p + 1]);
    }

#pragma unroll 4
    for (int f = 0; f < 64; ++f) {
        const unsigned long long a2 = pack2(xr[f], xr[f]);
#pragma unroll
        for (int oo = 0; oo < 32; oo += 4) {
            float4 w2 = *(const float4*)&W2s[f][oo];
            float4 wd = *(const float4*)&Wds[f][oo];
            fma2(ya2[oo / 2],     a2, pack2(w2.x, w2.y));
            fma2(ya2[oo / 2 + 1], a2, pack2(w2.z, w2.w));
            fma2(ca2[oo / 2],     a2, pack2(wd.x, wd.y));
            fma2(ca2[oo / 2 + 1], a2, pack2(wd.z, wd.w));
        }
    }
    float4* Yp = (float4*)(g_Yt + base);
    float4* Cp = (float4*)(g_Ct + base);
#pragma unroll
    for (int q = 0; q < 8; ++q) {
        float y0, y1, y2, y3, c0, c1, c2, c3;
        unpack2(ya2[2 * q], y0, y1);
        unpack2(ya2[2 * q + 1], y2, y3);
        unpack2(ca2[2 * q], c0, c1);
        unpack2(ca2[2 * q + 1], c2, c3);
        Yp[q] = make_float4(y0, y1, y2, y3);
        Cp[q] = make_float4(c0, c1, c2, c3);
    }
}

// ---------------------------------------------------------------------------
// Kernel 2 (FUSED): 128 rows per CTA, grid 256 (single wave), 8 warps (4x2),
// warp tile 32x32. Tiles 0..15: warp-coop top-26 -> threshold (smem) + seeds.
// Tiles 16..63: GEMM + in-register threshold scan + smem-atomic append.
// ---------------------------------------------------------------------------
#define DSS 66
#define SM_A    0                    // A: 128 rows x 128B = 16KB
#define SM_B    16384                // B: 2 bufs x 8KB = 16KB
#define SM_SQ   32768                // 2 bufs x 256B
#define SM_WS   33280                // wsm: 128 floats
#define SM_CNT  33792                // cnts: 128 ints
#define SM_D    34304                // Ds: 128 x 66 floats = 33792B
#define SM_TOT  (SM_D + 128 * DSS * 4)   // 68096

__global__ __launch_bounds__(256, 2) void k2_knn(void)
{
    extern __shared__ char sm[];
    const uint32_t smem_base = smem_u32(sm);
    float* Ds   = (float*)(sm + SM_D);
    float* wsm  = (float*)(sm + SM_WS);
    int*   cnts = (int*)(sm + SM_CNT);

    const int tid  = threadIdx.x;
    const int wid  = tid >> 5;
    const int lane = tid & 31;
    const int wr   = wid & 3;        // warp row group (32 rows)
    const int wc   = wid >> 2;       // warp col group (32 cols)

    const int bb = blockIdx.x >> 5;
    const int n0 = (blockIdx.x & 31) * 128;

    const __half* gp  = g_p + (size_t)bb * NPTS * 128;
    const float*  sqg = g_sq + (size_t)bb * NPTS;

    // ---- load A panel (hi only) swizzled: 128 rows x 8 chunks of 16B ----
    for (int idx = tid; idx < 1024; idx += 256) {
        int r = idx >> 3, ch = idx & 7;
        uint4 v = *(const uint4*)(gp + (size_t)(n0 + r) * 128 + ch * 8);
        *(uint4*)(sm + SM_A + r * 128 + ((ch ^ (r & 7)) << 4)) = v;
    }

    // ---- B tile loader (hi only, cp.async) ----
    auto loadB = [&](int t, int buf) {
        const __half* src0 = gp + (size_t)t * 64 * 128;
        uint32_t dst0 = smem_base + SM_B + buf * 8192;
#pragma unroll
        for (int k = 0; k < 2; ++k) {
            int idx = tid + k * 256;             // 0..511
            int r = idx >> 3, ch = idx & 7;
            CP_ASYNC16(dst0 + r * 128 + ((ch ^ (r & 7)) << 4),
                       src0 + (size_t)r * 128 + ch * 8);
        }
        if (tid < 16)
            CP_ASYNC16(smem_base + SM_SQ + buf * 256 + tid * 16,
                       sqg + t * 64 + tid * 4);
        CP_COMMIT();
    };

    // ---- GEMM one tile into acc (warp tile 32x32) ----
    const uint32_t abase = smem_base + SM_A;
    auto gemmTile = [&](int t, float acc[2][4][4]) {
#pragma unroll
        for (int mt = 0; mt < 2; ++mt)
#pragma unroll
            for (int nt = 0; nt < 4; ++nt)
#pragma unroll
                for (int e = 0; e < 4; ++e) acc[mt][nt][e] = 0.f;
        const uint32_t bbase = smem_base + SM_B + (t & 1) * 8192;
#pragma unroll
        for (int ks = 0; ks < 4; ++ks) {
            uint32_t ah[2][4], bh[2][4];
            const int acha = ks * 2 + (lane >> 4);
            const int bcha = ks * 2 + ((lane >> 3) & 1);
#pragma unroll
            for (int mt = 0; mt < 2; ++mt) {
                int row = wr * 32 + mt * 16 + (lane & 15);
                ldsm_x4(abase + row * 128 + ((acha ^ (row & 7)) << 4), ah[mt]);
            }
#pragma unroll
            for (int g = 0; g < 2; ++g) {
                int row = wc * 32 + g * 16 + (lane & 7) + ((lane >> 4) << 3);
                ldsm_x4(bbase + row * 128 + ((bcha ^ (row & 7)) << 4), bh[g]);
            }
#pragma unroll
            for (int mt = 0; mt < 2; ++mt)
#pragma unroll
                for (int nt = 0; nt < 4; ++nt)
                    mma16816(acc[mt][nt], ah[mt], &bh[nt >> 1][(nt & 1) * 2]);
        }
    };

    // ================= phase 1: sample tiles 0..15, top-26 per row =========
    unsigned lv[16];
#pragma unroll
    for (int r = 0; r < 16; ++r) lv[r] = 0xFFFFFFFFu;
    const int srow0 = wid * 16;

    loadB(0, 0);

#pragma unroll 1
    for (int t = 0; t < SMP; ++t) {
        CP_WAIT0();
        __syncthreads();                 // B[t]+sq visible; prev scans done
        loadB(t + 1, (t + 1) & 1);

        float acc[2][4][4];
        gemmTile(t, acc);

        // stage dot tile to Ds
#pragma unroll
        for (int mt = 0; mt < 2; ++mt) {
            int row0 = wr * 32 + mt * 16 + (lane >> 2);
#pragma unroll
            for (int nt = 0; nt < 4; ++nt) {
                int col0 = wc * 32 + nt * 8 + 2 * (lane & 3);
                Ds[row0 * DSS + col0]           = acc[mt][nt][0];
                Ds[row0 * DSS + col0 + 1]       = acc[mt][nt][1];
                Ds[(row0 + 8) * DSS + col0]     = acc[mt][nt][2];
                Ds[(row0 + 8) * DSS + col0 + 1] = acc[mt][nt][3];
            }
        }
        __syncthreads();

        // warp-coop top-26 over tile t
        const float2 sqv = *(const float2*)((const float*)(sm + SM_SQ + (t & 1) * 256)
                                            + 2 * lane);
        const int m0g = t * 64 + 2 * lane;
#pragma unroll
        for (int r = 0; r < 16; ++r) {
            const int nrowr = n0 + srow0 + r;
            const float2 d2 = *(const float2*)&Ds[(srow0 + r) * DSS + 2 * lane];
            const float k0 = fmaf(-2.0f, d2.x, sqv.x);
            const float k1 = fmaf(-2.0f, d2.y, sqv.y);
            const unsigned p0 = (m0g == nrowr)     ? 0xFFFFFFFFu : packkey(k0, m0g);
            const unsigned p1 = (m0g + 1 == nrowr) ? 0xFFFFFFFFu : packkey(k1, m0g + 1);

            const unsigned w = __shfl_sync(FULLMASK, lv[r], KA - 1);
            unsigned b = __ballot_sync(FULLMASK, min(p0, p1) < w);
            while (b) {
                const int s = __ffs(b) - 1;
                b &= b - 1;
                const unsigned P0 = __shfl_sync(FULLMASK, p0, s);
                const unsigned P1 = __shfl_sync(FULLMASK, p1, s);
#pragma unroll
                for (int e = 0; e < 2; ++e) {
                    const unsigned P = e ? P1 : P0;
                    if (P < w) {
                        const unsigned up = __shfl_up_sync(FULLMASK, lv[r], 1);
                        const bool pv    = lv[r] > P;
                        const bool pprev = (lane == 0) ? false : (up > P);
                        lv[r] = pv ? (pprev ? up : P) : lv[r];
                    }
                }
            }
        }
    }

    // ---- seed buffer, publish thresholds (smem), init counters ----
#pragma unroll
    for (int r = 0; r < 16; ++r) {
        const int rowl  = srow0 + r;
        const int growg = bb * NPTS + n0 + rowl;
        if (lane < KA) g_buf[(size_t)growg * CAP + lane] = lv[r];
        if (lane == KA - 1) {
            unsigned u = lv[r] & 0xFFFFF000u;            // trunc-down in key space
            u = (u & 0x80000000u) ? (u ^ 0x80000000u) : ~u;
            wsm[rowl] = __uint_as_float(u);
        }
    }
    if (tid < 128) cnts[tid] = KA;
    __syncthreads();

    // per-thread: the 4 rows this thread's accumulators cover
    int    rloc[4];
    size_t bufb[4];
    float  wf[4];
#pragma unroll
    for (int q = 0; q < 4; ++q) {
        const int rl = wr * 32 + (q >> 1) * 16 + (q & 1) * 8 + (lane >> 2);
        rloc[q] = rl;
        bufb[q] = (size_t)(bb * NPTS + n0 + rl) * CAP;
        wf[q]   = wsm[rl];
    }

    // ================= phase 2: tiles 16..63, threshold scan ==============
#pragma unroll 1
    for (int t = SMP; t < 64; ++t) {
        CP_WAIT0();
        __syncthreads();
        if (t + 1 < 64) loadB(t + 1, (t + 1) & 1);

        float acc[2][4][4];
        gemmTile(t, acc);

        const float* sqt = (const float*)(sm + SM_SQ + (t & 1) * 256);
#pragma unroll
        for (int mt = 0; mt < 2; ++mt)
#pragma unroll
            for (int nt = 0; nt < 4; ++nt) {
                const int cl = wc * 32 + nt * 8 + 2 * (lane & 3);
                const float2 sq2 = *(const float2*)&sqt[cl];
                const int c0 = t * 64 + cl;
#pragma unroll
                for (int h = 0; h < 2; ++h) {
                    const int q = mt * 2 + h;
                    const float k0 = fmaf(-2.0f, acc[mt][nt][h * 2 + 0], sq2.x);
                    const float k1 = fmaf(-2.0f, acc[mt][nt][h * 2 + 1], sq2.y);
                    if (fminf(k0, k1) < wf[q]) {
                        if (k0 < wf[q]) {
                            int pos = atomicAdd(&cnts[rloc[q]], 1);
                            if (pos < CAP) g_buf[bufb[q] + pos] = packkey(k0, c0);
                        }
                        if (k1 < wf[q]) {
                            int pos = atomicAdd(&cnts[rloc[q]], 1);
                            if (pos < CAP) g_buf[bufb[q] + pos] = packkey(k1, c0 + 1);
                        }
                    }
                }
            }
    }

    // ---- publish counts ----
    __syncthreads();
    if (tid < 128) g_cnt[bb * NPTS + n0 + tid] = cnts[tid];
}

// ---------------------------------------------------------------------------
// Kernel 2b: per-row approx-top-28 from buffer, then exact fp32 top-20
// grid 4096, 256 threads (8 warps = 8 rows per CTA)
// ---------------------------------------------------------------------------
__global__ __launch_bounds__(256) void k2b_refine(void)
{
    const int lane = threadIdx.x & 31;
    const int gw   = blockIdx.x * 8 + (threadIdx.x >> 5);
    const int bb   = gw >> 12;
    const int row  = gw & 4095;

    const __half* gp  = g_p + (size_t)bb * NPTS * 128;
    const float*  sqg = g_sq + (size_t)bb * NPTS;

    int cnt = g_cnt[gw];
    if (cnt > CAP) cnt = CAP;
    const unsigned* bufr = g_buf + (size_t)gw * CAP;

    // approx top-REFK (packed, distributed lanes 0..27)
    unsigned lv = 0xFFFFFFFFu;
#pragma unroll 1
    for (int base = 0; base < cnt; base += 32) {
        const unsigned p = (base + lane < cnt) ? bufr[base + lane] : 0xFFFFFFFFu;
        const unsigned w = __shfl_sync(FULLMASK, lv, REFK - 1);
        unsigned b = __ballot_sync(FULLMASK, p < w);
        while (b) {
            const int s = __ffs(b) - 1;
            b &= b - 1;
            const unsigned P = __shfl_sync(FULLMASK, p, s);
            if (P < w) {
                const unsigned up = __shfl_up_sync(FULLMASK, lv, 1);
                const bool pv    = lv > P;
                const bool pprev = (lane == 0) ? false : (up > P);
                lv = pv ? (pprev ? up : P) : lv;
            }
        }
    }

    // exact refine of the 28 survivors (skip self / empty slots)
    const unsigned* pn = (const unsigned*)(gp + (size_t)row * 128);
    const float2 an = h2pair(pn[lane], pn[32 + lane]);

    float mykey = BIGF;
    int   myidx = 0;
#pragma unroll 1
    for (int c = 0; c < REFK; c += 2) {
        const unsigned LA = __shfl_sync(FULLMASK, lv, c);
        const unsigned LB = __shfl_sync(FULLMASK, lv, c + 1);
        const int mA = (int)(LA & 0xFFFu);
        const int mB = (int)(LB & 0xFFFu);
        const unsigned* pA = (const unsigned*)(gp + (size_t)mA * 128);
        const unsigned* pB = (const unsigned*)(gp + (size_t)mB * 128);
        const float2 aA = h2pair(pA[lane], pA[32 + lane]);
        const float2 aB = h2pair(pB[lane], pB[32 + lane]);
        float pa = fmaf(an.x, aA.x, an.y * aA.y);
        float pb = fmaf(an.x, aB.x, an.y * aB.y);
#pragma unroll
        for (int s = 16; s >= 1; s >>= 1) {
            pa += __shfl_xor_sync(FULLMASK, pa, s);
            pb += __shfl_xor_sync(FULLMASK, pb, s);
        }
        float keyA = fmaf(-2.0f, pa, sqg[mA]);
        float keyB = fmaf(-2.0f, pb, sqg[mB]);
        if (LA == 0xFFFFFFFFu || mA == row) keyA = BIGF;
        if (LB == 0xFFFFFFFFu || mB == row) keyB = BIGF;
        if (lane == c)     { mykey = keyA; myidx = mA; }
        if (lane == c + 1) { mykey = keyB; myidx = mB; }
    }

    // exact top-20 select from the 28 exact keys
    float nv = BIGF; int ni = 0;
    float w = BIGF;
#pragma unroll 1
    for (int s = 0; s < REFK; ++s) {
        const float K = __shfl_sync(FULLMASK, mykey, s);
        const int   M = __shfl_sync(FULLMASK, myidx, s);
        if (K < w) {
            const float vprev = __shfl_up_sync(FULLMASK, nv, 1);
            const int   iprev = __shfl_up_sync(FULLMASK, ni, 1);
            const bool pv    = nv > K;
            const bool pprev = (lane == 0) ? false : (vprev > K);
            nv = pv ? (pprev ? vprev : K) : nv;
            ni = pv ? (pprev ? iprev : M) : ni;
            w = __shfl_sync(FULLMASK, nv, KNN - 1);
        }
    }
    if (lane < KNN)
        g_idx[(size_t)gw * KNN + lane] = ni;
}

// ---------------------------------------------------------------------------
// Kernel 3: gather-max epilogue + transpose to [b][o][n]
// ---------------------------------------------------------------------------
__global__ __launch_bounds__(256) void k3_epilogue(float* __restrict__ out)
{
    __shared__ float outs[64][65];
    const int bb  = blockIdx.y;
    const int n0  = blockIdx.x * 64;
    const int tid = threadIdx.x;
    const int w    = tid >> 5;
    const int lane = tid & 31;

    const float* Y = g_Yt + (size_t)bb * NPTS * 64;
    const float* C = g_Ct + (size_t)bb * NPTS * 64;

#pragma unroll 1
    for (int s = 0; s < 8; ++s) {
        int nn = w * 8 + s;
        int n  = n0 + nn;
        int jj = 0;
        if (lane < KNN) jj = g_idx[((size_t)(bb * NPTS + n)) * KNN + lane];
        float m0v = -3.0e38f, m1v = -3.0e38f;
#pragma unroll
        for (int i = 0; i < KNN; ++i) {
            int j = __shfl_sync(0xffffffffu, jj, i);
            const float* yr = Y + (size_t)j * 64;
            m0v = fmaxf(m0v, yr[lane]);
            m1v = fmaxf(m1v, yr[lane + 32]);
        }
        outs[nn][lane]      = m0v + C[(size_t)n * 64 + lane];
        outs[nn][lane + 32] = m1v + C[(size_t)n * 64 + lane + 32];
    }
    __syncthreads();

    float* ob = out + (size_t)bb * FOUT * NPTS;
#pragma unroll
    for (int it = 0; it < 16; ++it) {
        int lin = it * 256 + tid;
        int o  = lin >> 6;
        int nn = lin & 63;
        ob[o * NPTS + n0 + nn] = outs[nn][o];
    }
}

// ---------------------------------------------------------------------------
extern "C" void kernel_launch(void* const* d_in, const int* in_sizes, int n_in,
                              void* d_out, int out_size)
{
    const float* x    = (const float*)d_in[0];
    const float* W    = (const float*)d_in[1];
    const float* bvec = (const float*)d_in[2];
    float* out        = (float*)d_out;

    cudaFuncSetAttribute(k2_knn, cudaFuncAttributeMaxDynamicSharedMemorySize, SM_TOT);

    k1_features<<<dim3(NPTS / 128, BATCH, 2), 128>>>(x, W, bvec);
    k2_knn<<<BATCH * (NPTS / 128), 256, SM_TOT>>>();
    k2b_refine<<<BATCH * NPTS / 8, 256>>>();
    k3_epilogue<<<dim3(NPTS / 64, BATCH), 256>>>(out);
}